// round 9
// baseline (speedup 1.0000x reference)
#include <cuda_runtime.h>

// TranslateCube: out(y,x) = bilinear(in, y - ty, x - tx), zero fill.
// [B*T, 256, 256] fp32; (tx, ty) constant per image.
//
// R8 lesson: ptxas used 56 regs -> 4 blocks/SM -> 42% occ -> latency-bound.
// This round: __launch_bounds__(256, 6) forces regs<=40 (6 blocks, 75% occ),
// and the math is restructured row-interp-first (mk = wtop*a + wbot*b, then
// column interp) which cuts ops/row 48->40 and halves peak register liveness
// so the cap doesn't spill.

#define HH 256
#define WW 256
#define PX 8
#define TPR (WW / PX)        // 32 threads per row (one warp = one row)
#define WPB 8                // warps per block
#define RPT 2                // rows per thread
#define RPB (WPB * RPT)      // 16 rows per block

template <int M>
__device__ __forceinline__ void run_rows(
    const float* __restrict__ base, float4* __restrict__ obase,
    int yBase, int c, int qa, int qb, int qc,
    const float* __restrict__ u0, const float* __restrict__ u1, float ty)
{
#pragma unroll
    for (int r = 0; r < RPT; ++r) {
        const int y = yBase + r;
        const float sy  = (float)y - ty;
        const float y0f = floorf(sy);
        const float wy  = sy - y0f;
        const int   y0  = (int)y0f;
        const float wtop = ((unsigned)y0       < (unsigned)HH) ? (1.0f - wy) : 0.0f;
        const float wbot = ((unsigned)(y0 + 1) < (unsigned)HH) ? wy          : 0.0f;
        const int y0c = min(max(y0,     0), HH - 1);
        const int y1c = min(max(y0 + 1, 0), HH - 1);

        const float4* r0 = (const float4*)(base + (size_t)y0c * WW);
        const float4* r1 = (const float4*)(base + (size_t)y1c * WW);

        const float4 A0 = __ldg(r0 + qa), A1 = __ldg(r0 + qb), A2 = __ldg(r0 + qc);
        const float4 B0 = __ldg(r1 + qa), B1 = __ldg(r1 + qb), B2 = __ldg(r1 + qc);

        // Row interpolation first: collapses 24 live floats to 12.
        float mk[12];
        {
            const float va[12] = {A0.x, A0.y, A0.z, A0.w, A1.x, A1.y, A1.z, A1.w,
                                  A2.x, A2.y, A2.z, A2.w};
            const float vb[12] = {B0.x, B0.y, B0.z, B0.w, B1.x, B1.y, B1.z, B1.w,
                                  B2.x, B2.y, B2.z, B2.w};
#pragma unroll
            for (int k = 0; k < 12; ++k)
                mk[k] = fmaf(wbot, vb[k], wtop * va[k]);
        }

        float o[PX];
#pragma unroll
        for (int j = 0; j < PX; ++j)
            o[j] = fmaf(u1[j], mk[M + j + 1], u0[j] * mk[M + j]);

        float4* dst = &obase[y * (WW / 4) + c * 2];
        __stcs(dst,     make_float4(o[0], o[1], o[2], o[3]));
        __stcs(dst + 1, make_float4(o[4], o[5], o[6], o[7]));
    }
}

__global__ __launch_bounds__(256, 6) void translate_kernel(
    const float* __restrict__ img,
    const float* __restrict__ dx,
    const float* __restrict__ dy,
    float* __restrict__ out)
{
    const int imgIdx = blockIdx.y;
    const float tx = __ldg(dx + imgIdx);
    const float ty = __ldg(dy + imgIdx);

    const int c = threadIdx.x;                       // 0..31
    const int x = c * PX;
    const int yBase = blockIdx.x * RPB + threadIdx.y * RPT;

    const int   x0 = (int)floorf((float)x - tx);
    const int   m  = x0 & 3;                         // uniform per image
    const int   cbase = x0 - m;

    // Clamped, always-in-bounds float4 chunk indices (OOB lanes get 0 weight).
    const int qa = min(max(cbase,     0), WW - 4) >> 2;
    const int qb = min(max(cbase + 4, 0), WW - 4) >> 2;
    const int qc = min(max(cbase + 8, 0), WW - 4) >> 2;

    // Horizontal weights with column validity folded in (once per 16 px).
    float u0[PX], u1[PX];
#pragma unroll
    for (int j = 0; j < PX; ++j) {
        const float wx = ((float)(x + j) - tx) - (float)(x0 + j);
        const bool v0 = (unsigned)(x0 + j)     < (unsigned)WW;
        const bool v1 = (unsigned)(x0 + j + 1) < (unsigned)WW;
        u0[j] = v0 ? (1.0f - wx) : 0.0f;
        u1[j] = v1 ? wx          : 0.0f;
    }

    const float* base  = img + (size_t)imgIdx * (HH * WW);
    float4*      obase = (float4*)(out + (size_t)imgIdx * (HH * WW));

    switch (m) {
    case 0:  run_rows<0>(base, obase, yBase, c, qa, qb, qc, u0, u1, ty); break;
    case 1:  run_rows<1>(base, obase, yBase, c, qa, qb, qc, u0, u1, ty); break;
    case 2:  run_rows<2>(base, obase, yBase, c, qa, qb, qc, u0, u1, ty); break;
    default: run_rows<3>(base, obase, yBase, c, qa, qb, qc, u0, u1, ty); break;
    }
}

extern "C" void kernel_launch(void* const* d_in, const int* in_sizes, int n_in,
                              void* d_out, int out_size) {
    const float* images = (const float*)d_in[0];
    const float* dx     = (const float*)d_in[1];
    const float* dy     = (const float*)d_in[2];
    // d_in[3] is winsize (unused by the math)
    float* out = (float*)d_out;

    const int n_images = in_sizes[1];  // B*T

    dim3 block(TPR, WPB);              // 32 x 8 = 256 threads
    dim3 grid(HH / RPB, n_images);     // 16 x 1024
    translate_kernel<<<grid, block>>>(images, dx, dy, out);
}

// round 10
// speedup vs baseline: 1.1150x; 1.1150x over previous
#include <cuda_runtime.h>

// TranslateCube: out(y,x) = bilinear(in, y - ty, x - tx), zero fill.
// [B*T, 256, 256] fp32; (tx, ty) constant per image.
//
// R9 lesson: a 40-reg cap de-batched the 6xLDG.128 group (MLP collapse,
// issue 31%) and lost to R8 despite 62% occupancy. This round probes the
// intermediate point: __launch_bounds__(256,5) -> regs<=51, which still
// fits the full load batch (24 regs payload + addresses) while adding a
// 5th resident block (40 warps/SM).

#define HH 256
#define WW 256
#define PX 8
#define TPR (WW / PX)        // 32 threads per row (one warp = one row)
#define WPB 8                // warps per block
#define RPT 2                // rows per thread
#define RPB (WPB * RPT)      // 16 rows per block

template <int M>
__device__ __forceinline__ void run_rows(
    const float* __restrict__ base, float4* __restrict__ obase,
    int yBase, int c, int qa, int qb, int qc,
    const float* __restrict__ u0, const float* __restrict__ u1, float ty)
{
#pragma unroll
    for (int r = 0; r < RPT; ++r) {
        const int y = yBase + r;
        const float sy  = (float)y - ty;
        const float y0f = floorf(sy);
        const float wy  = sy - y0f;
        const int   y0  = (int)y0f;
        const float wtop = ((unsigned)y0       < (unsigned)HH) ? (1.0f - wy) : 0.0f;
        const float wbot = ((unsigned)(y0 + 1) < (unsigned)HH) ? wy          : 0.0f;
        const int y0c = min(max(y0,     0), HH - 1);
        const int y1c = min(max(y0 + 1, 0), HH - 1);

        const float4* r0 = (const float4*)(base + (size_t)y0c * WW);
        const float4* r1 = (const float4*)(base + (size_t)y1c * WW);

        const float4 A0 = __ldg(r0 + qa), A1 = __ldg(r0 + qb), A2 = __ldg(r0 + qc);
        const float4 B0 = __ldg(r1 + qa), B1 = __ldg(r1 + qb), B2 = __ldg(r1 + qc);

        const float va[12] = {A0.x, A0.y, A0.z, A0.w, A1.x, A1.y, A1.z, A1.w,
                              A2.x, A2.y, A2.z, A2.w};
        const float vb[12] = {B0.x, B0.y, B0.z, B0.w, B1.x, B1.y, B1.z, B1.w,
                              B2.x, B2.y, B2.z, B2.w};

        float o[PX];
#pragma unroll
        for (int j = 0; j < PX; ++j) {
            const float t = fmaf(u1[j], va[M + j + 1], u0[j] * va[M + j]);
            const float s = fmaf(u1[j], vb[M + j + 1], u0[j] * vb[M + j]);
            o[j] = fmaf(wbot, s, wtop * t);
        }
        float4* dst = &obase[y * (WW / 4) + c * 2];
        __stcs(dst,     make_float4(o[0], o[1], o[2], o[3]));
        __stcs(dst + 1, make_float4(o[4], o[5], o[6], o[7]));
    }
}

__global__ __launch_bounds__(256, 5) void translate_kernel(
    const float* __restrict__ img,
    const float* __restrict__ dx,
    const float* __restrict__ dy,
    float* __restrict__ out)
{
    const int imgIdx = blockIdx.y;
    const float tx = __ldg(dx + imgIdx);
    const float ty = __ldg(dy + imgIdx);

    const int c = threadIdx.x;                       // 0..31
    const int x = c * PX;
    const int yBase = blockIdx.x * RPB + threadIdx.y * RPT;

    const int   x0 = (int)floorf((float)x - tx);
    const int   m  = x0 & 3;                         // uniform per image
    const int   cbase = x0 - m;

    // Clamped, always-in-bounds float4 chunk indices (OOB lanes get 0 weight).
    const int qa = min(max(cbase,     0), WW - 4) >> 2;
    const int qb = min(max(cbase + 4, 0), WW - 4) >> 2;
    const int qc = min(max(cbase + 8, 0), WW - 4) >> 2;

    // Horizontal weights with column validity folded in (once per 16 px).
    float u0[PX], u1[PX];
#pragma unroll
    for (int j = 0; j < PX; ++j) {
        const float wx = ((float)(x + j) - tx) - (float)(x0 + j);
        const bool v0 = (unsigned)(x0 + j)     < (unsigned)WW;
        const bool v1 = (unsigned)(x0 + j + 1) < (unsigned)WW;
        u0[j] = v0 ? (1.0f - wx) : 0.0f;
        u1[j] = v1 ? wx          : 0.0f;
    }

    const float* base  = img + (size_t)imgIdx * (HH * WW);
    float4*      obase = (float4*)(out + (size_t)imgIdx * (HH * WW));

    switch (m) {
    case 0:  run_rows<0>(base, obase, yBase, c, qa, qb, qc, u0, u1, ty); break;
    case 1:  run_rows<1>(base, obase, yBase, c, qa, qb, qc, u0, u1, ty); break;
    case 2:  run_rows<2>(base, obase, yBase, c, qa, qb, qc, u0, u1, ty); break;
    default: run_rows<3>(base, obase, yBase, c, qa, qb, qc, u0, u1, ty); break;
    }
}

extern "C" void kernel_launch(void* const* d_in, const int* in_sizes, int n_in,
                              void* d_out, int out_size) {
    const float* images = (const float*)d_in[0];
    const float* dx     = (const float*)d_in[1];
    const float* dy     = (const float*)d_in[2];
    // d_in[3] is winsize (unused by the math)
    float* out = (float*)d_out;

    const int n_images = in_sizes[1];  // B*T

    dim3 block(TPR, WPB);              // 32 x 8 = 256 threads
    dim3 grid(HH / RPB, n_images);     // 16 x 1024
    translate_kernel<<<grid, block>>>(images, dx, dy, out);
}